// round 7
// baseline (speedup 1.0000x reference)
#include <cuda_runtime.h>
#include <math.h>

// Problem constants
constexpr int kB = 64, kN = 1024, kF = 16, kD = 64, kK = 20;
constexpr int kM = kB * kN;              // 65536 rows
constexpr float kEps = 1e-5f, kSlope = 0.2f;

// ---------------- scratch (device globals: allocation-free) ----------------
__device__ float  g_h[(size_t)kM * kD];      // 16 MB: h = data @ lin_w^T
__device__ float  g_out1[(size_t)kM * kD];   // 16 MB: pre-BN1 GNN output
__device__ float  g_si[kM];
__device__ float  g_sj[kM];
__device__ float  g_emi[kN];
__device__ float  g_emj[kN];
__device__ float  g_cos[(size_t)kN * kN];    // 4 MB cosine Gram
__device__ int    g_idx[kN * kK];            // top-k index sets
__device__ double g_sum1[kD], g_ssq1[kD], g_sum2[kD], g_ssq2[kD];

// ---------------- kernel 1: cosine Gram + norms + emb-att dots + zeroing ----
__global__ void k_cos(const float* __restrict__ emb,
                      const float* __restrict__ aei,
                      const float* __restrict__ aej) {
    __shared__ float As[kD][65];   // [k][row], padded
    __shared__ float Bs[kD][65];
    __shared__ float rnA[64], rnB[64];
    int t = threadIdx.x;
    int bn = blockIdx.y * 64, bm = blockIdx.x * 64;
    if (blockIdx.x == 0 && blockIdx.y == 0 && t < kD) {
        g_sum1[t] = 0.0; g_ssq1[t] = 0.0; g_sum2[t] = 0.0; g_ssq2[t] = 0.0;
    }
    for (int idx = t; idx < 64 * 64; idx += 256) {
        int r = idx >> 6, k = idx & 63;
        As[k][r] = emb[(size_t)(bn + r) * kD + k];
        Bs[k][r] = emb[(size_t)(bm + r) * kD + k];
    }
    __syncthreads();
    // row norms (threads 0..127) and per-row emb-att dots (threads 128..255,
    // only the blockIdx.x==0 column of blocks, covering all 1024 rows)
    if (t < 64) {
        float s = 0.f;
        for (int k = 0; k < 64; k++) { float v = As[k][t]; s += v * v; }
        rnA[t] = 1.0f / sqrtf(s);
    } else if (t < 128) {
        int r = t - 64;
        float s = 0.f;
        for (int k = 0; k < 64; k++) { float v = Bs[k][r]; s += v * v; }
        rnB[r] = 1.0f / sqrtf(s);
    } else if (blockIdx.x == 0) {
        int r = (t - 128) & 63;
        const float* av = (t < 192) ? aei : aej;
        float s = 0.f;
        for (int k = 0; k < 64; k++) s += As[k][r] * av[k];
        if (t < 192) g_emi[bn + r] = s; else g_emj[bn + r] = s;
    }
    // 64x64x64 register-tiled GEMM
    int tx = t & 15, ty = t >> 4;
    float acc[4][4] = {};
#pragma unroll 4
    for (int k = 0; k < 64; k++) {
        float a[4], b[4];
#pragma unroll
        for (int i = 0; i < 4; i++) { a[i] = As[k][ty * 4 + i]; b[i] = Bs[k][tx * 4 + i]; }
#pragma unroll
        for (int i = 0; i < 4; i++)
#pragma unroll
            for (int j = 0; j < 4; j++) acc[i][j] += a[i] * b[j];
    }
    __syncthreads();   // rnA/rnB ready
#pragma unroll
    for (int i = 0; i < 4; i++) {
        int r = bn + ty * 4 + i;
        float rn = rnA[ty * 4 + i];
#pragma unroll
        for (int j = 0; j < 4; j++) {
            int c = bm + tx * 4 + j;
            g_cos[(size_t)r * kN + c] = acc[i][j] * rn * rnB[tx * 4 + j];
        }
    }
}

// ---------------- kernel 2: h = data @ lin_w^T, plus s_i / s_j --------------
__global__ void k_h(const float* __restrict__ data, const float* __restrict__ lin_w,
                    const float* __restrict__ att_i, const float* __restrict__ att_j) {
    __shared__ float lw[kF][kD];
    for (int idx = threadIdx.x; idx < kF * kD; idx += blockDim.x) {
        int f = idx >> 6, d = idx & 63;
        lw[f][d] = lin_w[d * kF + f];
    }
    __syncthreads();
    int lane = threadIdx.x & 31;
    int gw = (blockIdx.x * blockDim.x + threadIdx.x) >> 5;
    int nw = (gridDim.x * blockDim.x) >> 5;
    float ai0 = att_i[lane], ai1 = att_i[lane + 32];
    float aj0 = att_j[lane], aj1 = att_j[lane + 32];
    for (int r = gw; r < kM; r += nw) {
        const float4* dp = reinterpret_cast<const float4*>(data + (size_t)r * kF);
        float4 q0 = dp[0], q1 = dp[1], q2 = dp[2], q3 = dp[3];
        float df[16] = {q0.x, q0.y, q0.z, q0.w, q1.x, q1.y, q1.z, q1.w,
                        q2.x, q2.y, q2.z, q2.w, q3.x, q3.y, q3.z, q3.w};
        float h0 = 0.f, h1 = 0.f;
#pragma unroll
        for (int f = 0; f < 16; f++) {
            h0 += df[f] * lw[f][lane];
            h1 += df[f] * lw[f][lane + 32];
        }
        g_h[(size_t)r * kD + lane] = h0;
        g_h[(size_t)r * kD + lane + 32] = h1;
        float si = h0 * ai0 + h1 * ai1;
        float sj = h0 * aj0 + h1 * aj1;
#pragma unroll
        for (int o = 16; o; o >>= 1) {
            si += __shfl_xor_sync(0xffffffffu, si, o);
            sj += __shfl_xor_sync(0xffffffffu, sj, o);
        }
        if (lane == 0) {
            int n = r & (kN - 1);
            g_si[r] = si + g_emi[n];
            g_sj[r] = sj + g_emj[n];
        }
    }
}

// ---------------- kernel 3: exact top-20 via 4-pass 8-bit radix select ------
// Set semantics (order in g_idx irrelevant); ties at the threshold take the
// lowest indices, matching jax.lax.top_k's stable selection set.
__global__ void k_topk() {
    __shared__ unsigned sv[kN];
    __shared__ int hist[256];
    __shared__ int suf[256];
    __shared__ int tie[kN];
    __shared__ int s_digit, s_above, s_need, s_cntA, s_cntT, s_sel;
    __shared__ int wmin[8];
    int n = blockIdx.x, t = threadIdx.x;
    int lane = t & 31, wid = t >> 5;
    const unsigned* row = reinterpret_cast<const unsigned*>(g_cos + (size_t)n * kN);
#pragma unroll
    for (int i = 0; i < 4; i++) {
        unsigned x = row[t + 256 * i];
        x ^= (x & 0x80000000u) ? 0xFFFFFFFFu : 0x80000000u;  // order-preserving
        sv[t + 256 * i] = x;
    }
    if (t == 0) { s_need = kK; s_cntA = 0; s_cntT = 0; }
    unsigned prefix = 0;
    for (int shift = 24; shift >= 0; shift -= 8) {
        hist[t] = 0;
        __syncthreads();
        unsigned mask = (shift == 24) ? 0u : (0xFFFFFFFFu << (shift + 8));
#pragma unroll
        for (int i = 0; i < 4; i++) {
            unsigned x = sv[t + 256 * i];
            if ((x & mask) == prefix) atomicAdd(&hist[(x >> shift) & 0xFF], 1);
        }
        __syncthreads();
        if (wid == 0) {  // suffix sums: suf[e] = count of digit >= e
            int base = 255 - 8 * lane;
            int loc[8], s = 0;
#pragma unroll
            for (int j = 0; j < 8; j++) { loc[j] = hist[base - j]; s += loc[j]; }
            int run = s;
#pragma unroll
            for (int off = 1; off < 32; off <<= 1) {
                int v = __shfl_up_sync(0xffffffffu, run, off);
                if (lane >= off) run += v;
            }
            int acc = run - s;  // sum over lanes with higher bins
#pragma unroll
            for (int j = 0; j < 8; j++) { acc += loc[j]; suf[base - j] = acc; }
        }
        __syncthreads();
        int need = s_need;
        int above = (t == 255) ? 0 : suf[t + 1];
        if (suf[t] >= need && above < need) { s_digit = t; s_above = above; }
        __syncthreads();
        prefix |= ((unsigned)s_digit) << shift;
        if (t == 0) s_need -= s_above;
        __syncthreads();
    }
    unsigned T = prefix;  // exact K-th largest (transformed)
#pragma unroll
    for (int i = 0; i < 4; i++) {
        int m = t + 256 * i;
        unsigned x = sv[m];
        if (x > T)      { int p = atomicAdd(&s_cntA, 1); g_idx[n * kK + p] = m; }
        else if (x == T){ int p = atomicAdd(&s_cntT, 1); tie[p] = m; }
    }
    __syncthreads();
    int needT = kK - s_cntA;
    if (s_cntT == needT) {
        if (t < needT) g_idx[n * kK + s_cntA + t] = tie[t];
    } else {
        // rare: choose needT lowest indices among the ties
        for (int r = 0; r < needT; r++) {
            int best = 0x7fffffff;
            for (int i = t; i < s_cntT; i += 256) best = min(best, tie[i]);
#pragma unroll
            for (int o = 16; o; o >>= 1) best = min(best, __shfl_xor_sync(0xffffffffu, best, o));
            if (lane == 0) wmin[wid] = best;
            __syncthreads();
            if (t == 0) {
                int m = 0x7fffffff;
                for (int w = 0; w < 8; w++) m = min(m, wmin[w]);
                g_idx[n * kK + s_cntA + r] = m;
                s_sel = m;
            }
            __syncthreads();
            for (int i = t; i < s_cntT; i += 256) if (tie[i] == s_sel) tie[i] = 0x7fffffff;
            __syncthreads();
        }
    }
}

// ---------------- kernel 4: softmax + smem-staged gather + BN1 stats --------
// One block per (b, d-half). h[b][:, half] (128 KB) staged once; the K-way
// gather (335 MB aggregate) is served from shared memory, not L2.
constexpr int kMainSmem = (kN * 32 + kN) * 4;   // tile + s_j  = 135168 B
__global__ void k_main(const float* __restrict__ gnn_bias) {
    extern __shared__ float sm[];
    float* sh  = sm;             // [1024][32]
    float* ssj = sm + kN * 32;   // [1024]
    __shared__ float rs[8][32], rq[8][32];
    int t = threadIdx.x, lane = t & 31, wid = t >> 5;
    int b = blockIdx.x >> 1, half = blockIdx.x & 1;
    int d = half * 32 + lane;
    const float* hb = g_h + (size_t)b * kN * kD;
    for (int i = t; i < kN * 32; i += 256)
        sh[i] = hb[(size_t)(i >> 5) * kD + half * 32 + (i & 31)];
    for (int i = t; i < kN; i += 256) ssj[i] = g_sj[b * kN + i];
    __syncthreads();
    float bias = gnn_bias[d];
    float ts = 0.f, tq = 0.f;
    for (int n = wid; n < kN; n += 8) {
        float si = g_si[b * kN + n];
        float a = -INFINITY; int id = 0;
        if (lane < kK) {
            id = g_idx[n * kK + lane];
            a = si + ssj[id];
            a = a > 0.f ? a : kSlope * a;    // leaky_relu(0.2)
        }
        float mx = a;
#pragma unroll
        for (int o = 16; o; o >>= 1) mx = fmaxf(mx, __shfl_xor_sync(0xffffffffu, mx, o));
        float e = (lane < kK) ? expf(a - mx) : 0.f;
        float s = e;
#pragma unroll
        for (int o = 16; o; o >>= 1) s += __shfl_xor_sync(0xffffffffu, s, o);
        float alpha = e / s;
        float acc = 0.f;
#pragma unroll
        for (int k = 0; k < kK; k++) {
            float w  = __shfl_sync(0xffffffffu, alpha, k);
            int   ik = __shfl_sync(0xffffffffu, id, k);
            acc += w * sh[ik * 32 + lane];
        }
        float o = acc + bias;
        g_out1[((size_t)(b * kN + n)) * kD + d] = o;
        ts += o; tq += o * o;
    }
    rs[wid][lane] = ts; rq[wid][lane] = tq;
    __syncthreads();
    if (t < 32) {
        float s = 0.f, q = 0.f;
        for (int w = 0; w < 8; w++) { s += rs[w][t]; q += rq[w][t]; }
        atomicAdd(&g_sum1[half * 32 + t], (double)s);
        atomicAdd(&g_ssq1[half * 32 + t], (double)q);
    }
}

// ---------------- BN affine finalize (inlined by consumers) -----------------
__device__ __forceinline__ void bn_ab(int d, const float* gm, const float* bt,
                                      const double* S, const double* Q,
                                      float& a, float& b) {
    double m = S[d] / (double)kM;
    double var = Q[d] / (double)kM - m * m;
    float inv = (float)(1.0 / sqrt(var + (double)kEps));
    a = gm[d] * inv;
    b = bt[d] - (float)m * a;
}

// ---------------- kernel 5: BN2 statistics ----------------------------------
__global__ void k_stats2(const float* __restrict__ emb,
                         const float* __restrict__ g1, const float* __restrict__ b1v) {
    int t = threadIdx.x;
    int c = t & 63, rg = t >> 6;
    float a1, b1; bn_ab(c, g1, b1v, g_sum1, g_ssq1, a1, b1);
    float ts = 0.f, tq = 0.f;
    int r0 = blockIdx.x * 64;
    for (int i = 0; i < 16; i++) {
        int r = r0 + rg * 16 + i;
        float x = g_out1[(size_t)r * kD + c];
        float y = fmaxf(fmaf(a1, x, b1), 0.f);
        float rep = y * emb[(size_t)(r & (kN - 1)) * kD + c];
        ts += rep; tq += rep * rep;
    }
    __shared__ float rs[4][kD], rq[4][kD];
    rs[rg][c] = ts; rq[rg][c] = tq;
    __syncthreads();
    if (t < kD) {
        float s = 0.f, q = 0.f;
        for (int g = 0; g < 4; g++) { s += rs[g][t]; q += rq[g][t]; }
        atomicAdd(&g_sum2[t], (double)s);
        atomicAdd(&g_ssq2[t], (double)q);
    }
}

// ---------------- kernel 6: final projection --------------------------------
__global__ void k_final(const float* __restrict__ emb, const float* __restrict__ out_w,
                        const float* __restrict__ out_b,
                        const float* __restrict__ g1, const float* __restrict__ b1v,
                        const float* __restrict__ g2, const float* __restrict__ b2v,
                        float* __restrict__ out) {
    int lane = threadIdx.x & 31;
    int gw = (blockIdx.x * blockDim.x + threadIdx.x) >> 5;
    int nw = (gridDim.x * blockDim.x) >> 5;
    float a10, b10, a11, b11, a20, b20, a21, b21;
    bn_ab(lane,      g1, b1v, g_sum1, g_ssq1, a10, b10);
    bn_ab(lane + 32, g1, b1v, g_sum1, g_ssq1, a11, b11);
    bn_ab(lane,      g2, b2v, g_sum2, g_ssq2, a20, b20);
    bn_ab(lane + 32, g2, b2v, g_sum2, g_ssq2, a21, b21);
    float w0 = out_w[lane], w1 = out_w[lane + 32];
    float ob = out_b[0];
    for (int r = gw; r < kM; r += nw) {
        int n = r & (kN - 1);
        float x0 = g_out1[(size_t)r * kD + lane];
        float x1 = g_out1[(size_t)r * kD + lane + 32];
        float y0 = fmaxf(fmaf(a10, x0, b10), 0.f) * emb[(size_t)n * kD + lane];
        float y1 = fmaxf(fmaf(a11, x1, b11), 0.f) * emb[(size_t)n * kD + lane + 32];
        float z0 = fmaxf(fmaf(a20, y0, b20), 0.f);
        float z1 = fmaxf(fmaf(a21, y1, b21), 0.f);
        float sred = z0 * w0 + z1 * w1;
#pragma unroll
        for (int o = 16; o; o >>= 1) sred += __shfl_xor_sync(0xffffffffu, sred, o);
        if (lane == 0) out[r] = sred + ob;
    }
}

// ---------------- launch ----------------------------------------------------
extern "C" void kernel_launch(void* const* d_in, const int* in_sizes, int n_in,
                              void* d_out, int out_size) {
    const float* data     = (const float*)d_in[0];
    // d_in[1] = org_edge_index (int64) — unused by the reference
    const float* emb      = (const float*)d_in[2];
    const float* lin_w    = (const float*)d_in[3];
    const float* att_i    = (const float*)d_in[4];
    const float* att_j    = (const float*)d_in[5];
    const float* aei      = (const float*)d_in[6];
    const float* aej      = (const float*)d_in[7];
    const float* gnn_bias = (const float*)d_in[8];
    const float* g1       = (const float*)d_in[9];
    const float* b1       = (const float*)d_in[10];
    const float* g2       = (const float*)d_in[11];
    const float* b2       = (const float*)d_in[12];
    const float* out_w    = (const float*)d_in[13];
    const float* out_b    = (const float*)d_in[14];
    float* out = (float*)d_out;

    cudaFuncSetAttribute(k_main, cudaFuncAttributeMaxDynamicSharedMemorySize, kMainSmem);

    k_cos<<<dim3(16, 16), 256>>>(emb, aei, aej);
    k_h<<<2048, 256>>>(data, lin_w, att_i, att_j);
    k_topk<<<1024, 256>>>();
    k_main<<<128, 256, kMainSmem>>>(gnn_bias);
    k_stats2<<<1024, 256>>>(emb, g1, b1);
    k_final<<<512, 256>>>(emb, out_w, out_b, g1, b1, g2, b2, out);
}

// round 9
// speedup vs baseline: 1.5216x; 1.5216x over previous
#include <cuda_runtime.h>
#include <math.h>

// Problem constants
constexpr int kB = 64, kN = 1024, kF = 16, kD = 64, kK = 20;
constexpr int kM = kB * kN;              // 65536 rows
constexpr float kEps = 1e-5f, kSlope = 0.2f;

// ---------------- scratch (device globals: allocation-free) ----------------
__device__ float  g_h[(size_t)kM * kD];      // 16 MB: h = data @ lin_w^T
__device__ float  g_out1[(size_t)kM * kD];   // 16 MB: pre-BN1 GNN output
__device__ float  g_si[kM];
__device__ float  g_sj[kM];
__device__ float  g_emi[kN];
__device__ float  g_emj[kN];
__device__ float  g_cos[(size_t)kN * kN];    // 4 MB cosine Gram
__device__ int    g_idx[kN * kK];            // top-k index sets
__device__ double g_sum1[kD], g_ssq1[kD], g_sum2[kD], g_ssq2[kD];

// ---------------- kernel 1: cosine Gram + norms + emb-att dots + zeroing ----
__global__ void k_cos(const float* __restrict__ emb,
                      const float* __restrict__ aei,
                      const float* __restrict__ aej) {
    __shared__ float As[kD][65];   // [k][row], padded
    __shared__ float Bs[kD][65];
    __shared__ float rnA[64], rnB[64];
    int t = threadIdx.x;
    int bn = blockIdx.y * 64, bm = blockIdx.x * 64;
    if (blockIdx.x == 0 && blockIdx.y == 0 && t < kD) {
        g_sum1[t] = 0.0; g_ssq1[t] = 0.0; g_sum2[t] = 0.0; g_ssq2[t] = 0.0;
    }
    for (int idx = t; idx < 64 * 64; idx += 256) {
        int r = idx >> 6, k = idx & 63;
        As[k][r] = emb[(size_t)(bn + r) * kD + k];
        Bs[k][r] = emb[(size_t)(bm + r) * kD + k];
    }
    __syncthreads();
    if (t < 64) {
        float s = 0.f;
        for (int k = 0; k < 64; k++) { float v = As[k][t]; s += v * v; }
        rnA[t] = 1.0f / sqrtf(s);
    } else if (t < 128) {
        int r = t - 64;
        float s = 0.f;
        for (int k = 0; k < 64; k++) { float v = Bs[k][r]; s += v * v; }
        rnB[r] = 1.0f / sqrtf(s);
    } else if (blockIdx.x == 0) {
        int r = (t - 128) & 63;
        const float* av = (t < 192) ? aei : aej;
        float s = 0.f;
        for (int k = 0; k < 64; k++) s += As[k][r] * av[k];
        if (t < 192) g_emi[bn + r] = s; else g_emj[bn + r] = s;
    }
    int tx = t & 15, ty = t >> 4;
    float acc[4][4] = {};
#pragma unroll 4
    for (int k = 0; k < 64; k++) {
        float a[4], b[4];
#pragma unroll
        for (int i = 0; i < 4; i++) { a[i] = As[k][ty * 4 + i]; b[i] = Bs[k][tx * 4 + i]; }
#pragma unroll
        for (int i = 0; i < 4; i++)
#pragma unroll
            for (int j = 0; j < 4; j++) acc[i][j] += a[i] * b[j];
    }
    __syncthreads();
#pragma unroll
    for (int i = 0; i < 4; i++) {
        int r = bn + ty * 4 + i;
        float rn = rnA[ty * 4 + i];
#pragma unroll
        for (int j = 0; j < 4; j++) {
            int c = bm + tx * 4 + j;
            g_cos[(size_t)r * kN + c] = acc[i][j] * rn * rnB[tx * 4 + j];
        }
    }
}

// ---------------- kernel 2: h = data @ lin_w^T, plus s_i / s_j --------------
__global__ void k_h(const float* __restrict__ data, const float* __restrict__ lin_w,
                    const float* __restrict__ att_i, const float* __restrict__ att_j) {
    __shared__ float lw[kF][kD];
    for (int idx = threadIdx.x; idx < kF * kD; idx += blockDim.x) {
        int f = idx >> 6, d = idx & 63;
        lw[f][d] = lin_w[d * kF + f];
    }
    __syncthreads();
    int lane = threadIdx.x & 31;
    int gw = (blockIdx.x * blockDim.x + threadIdx.x) >> 5;
    int nw = (gridDim.x * blockDim.x) >> 5;
    float ai0 = att_i[lane], ai1 = att_i[lane + 32];
    float aj0 = att_j[lane], aj1 = att_j[lane + 32];
    for (int r = gw; r < kM; r += nw) {
        const float4* dp = reinterpret_cast<const float4*>(data + (size_t)r * kF);
        float4 q0 = dp[0], q1 = dp[1], q2 = dp[2], q3 = dp[3];
        float df[16] = {q0.x, q0.y, q0.z, q0.w, q1.x, q1.y, q1.z, q1.w,
                        q2.x, q2.y, q2.z, q2.w, q3.x, q3.y, q3.z, q3.w};
        float h0 = 0.f, h1 = 0.f;
#pragma unroll
        for (int f = 0; f < 16; f++) {
            h0 += df[f] * lw[f][lane];
            h1 += df[f] * lw[f][lane + 32];
        }
        g_h[(size_t)r * kD + lane] = h0;
        g_h[(size_t)r * kD + lane + 32] = h1;
        float si = h0 * ai0 + h1 * ai1;
        float sj = h0 * aj0 + h1 * aj1;
#pragma unroll
        for (int o = 16; o; o >>= 1) {
            si += __shfl_xor_sync(0xffffffffu, si, o);
            sj += __shfl_xor_sync(0xffffffffu, sj, o);
        }
        if (lane == 0) {
            int n = r & (kN - 1);
            g_si[r] = si + g_emi[n];
            g_sj[r] = sj + g_emj[n];
        }
    }
}

// ---------------- kernel 3: exact top-20 via 4-pass 8-bit radix select ------
__global__ void k_topk() {
    __shared__ unsigned sv[kN];
    __shared__ int hist[256];
    __shared__ int suf[256];
    __shared__ int tie[kN];
    __shared__ int s_digit, s_above, s_need, s_cntA, s_cntT, s_sel;
    __shared__ int wmin[8];
    int n = blockIdx.x, t = threadIdx.x;
    int lane = t & 31, wid = t >> 5;
    const unsigned* row = reinterpret_cast<const unsigned*>(g_cos + (size_t)n * kN);
#pragma unroll
    for (int i = 0; i < 4; i++) {
        unsigned x = row[t + 256 * i];
        x ^= (x & 0x80000000u) ? 0xFFFFFFFFu : 0x80000000u;  // order-preserving
        sv[t + 256 * i] = x;
    }
    if (t == 0) { s_need = kK; s_cntA = 0; s_cntT = 0; }
    unsigned prefix = 0;
    for (int shift = 24; shift >= 0; shift -= 8) {
        hist[t] = 0;
        __syncthreads();
        unsigned mask = (shift == 24) ? 0u : (0xFFFFFFFFu << (shift + 8));
#pragma unroll
        for (int i = 0; i < 4; i++) {
            unsigned x = sv[t + 256 * i];
            if ((x & mask) == prefix) atomicAdd(&hist[(x >> shift) & 0xFF], 1);
        }
        __syncthreads();
        if (wid == 0) {  // suffix sums: suf[e] = count of digit >= e
            int base = 255 - 8 * lane;
            int loc[8], s = 0;
#pragma unroll
            for (int j = 0; j < 8; j++) { loc[j] = hist[base - j]; s += loc[j]; }
            int run = s;
#pragma unroll
            for (int off = 1; off < 32; off <<= 1) {
                int v = __shfl_up_sync(0xffffffffu, run, off);
                if (lane >= off) run += v;
            }
            int acc = run - s;
#pragma unroll
            for (int j = 0; j < 8; j++) { acc += loc[j]; suf[base - j] = acc; }
        }
        __syncthreads();
        int need = s_need;
        int above = (t == 255) ? 0 : suf[t + 1];
        if (suf[t] >= need && above < need) { s_digit = t; s_above = above; }
        __syncthreads();
        prefix |= ((unsigned)s_digit) << shift;
        if (t == 0) s_need -= s_above;
        __syncthreads();
    }
    unsigned T = prefix;  // exact K-th largest (transformed)
#pragma unroll
    for (int i = 0; i < 4; i++) {
        int m = t + 256 * i;
        unsigned x = sv[m];
        if (x > T)      { int p = atomicAdd(&s_cntA, 1); g_idx[n * kK + p] = m; }
        else if (x == T){ int p = atomicAdd(&s_cntT, 1); tie[p] = m; }
    }
    __syncthreads();
    int needT = kK - s_cntA;
    if (s_cntT == needT) {
        if (t < needT) g_idx[n * kK + s_cntA + t] = tie[t];
    } else {
        for (int r = 0; r < needT; r++) {
            int best = 0x7fffffff;
            for (int i = t; i < s_cntT; i += 256) best = min(best, tie[i]);
#pragma unroll
            for (int o = 16; o; o >>= 1) best = min(best, __shfl_xor_sync(0xffffffffu, best, o));
            if (lane == 0) wmin[wid] = best;
            __syncthreads();
            if (t == 0) {
                int m = 0x7fffffff;
                for (int w = 0; w < 8; w++) m = min(m, wmin[w]);
                g_idx[n * kK + s_cntA + r] = m;
                s_sel = m;
            }
            __syncthreads();
            for (int i = t; i < s_cntT; i += 256) if (tie[i] == s_sel) tie[i] = 0x7fffffff;
            __syncthreads();
        }
    }
}

// ---------------- kernel 4: softmax + L1-resident gather + BN1 stats --------
// One block of 1024 threads (32 warps) per (b, d-half). Gather working set is
// 1024 rows x 128B (one L1 line per row-half) = 128 KB -> stays L1-resident.
// Alpha/id packed to a tiny smem strip so the gather loop issues one LDS.128
// broadcast per 2 k and one LDG per k (no SHFL chains).
__global__ void __launch_bounds__(1024, 1) k_main(const float* __restrict__ gnn_bias) {
    __shared__ float  ssj[kN];                 // 4 KB
    __shared__ float4 sp[32][10];              // 5 KB: per-warp packed (a,id)x2
    __shared__ float  rs[32][32], rq[32][32];  // 8 KB
    int t = threadIdx.x, lane = t & 31, wid = t >> 5;
    int b = blockIdx.x >> 1, half = blockIdx.x & 1;
    const float* hb = g_h + (size_t)b * kN * kD + half * 32;
    for (int i = t; i < kN; i += 1024) ssj[i] = g_sj[b * kN + i];
    __syncthreads();
    float bias = gnn_bias[half * 32 + lane];
    float ts = 0.f, tq = 0.f;
    const float* sib = g_si + b * kN;
    for (int n = wid; n < kN; n += 32) {
        float si = sib[n];
        float a = -INFINITY; int id = 0;
        if (lane < kK) {
            id = g_idx[n * kK + lane];
            a = si + ssj[id];
            a = a > 0.f ? a : kSlope * a;      // leaky_relu(0.2)
        }
        float mx = a;
#pragma unroll
        for (int o = 16; o; o >>= 1) mx = fmaxf(mx, __shfl_xor_sync(0xffffffffu, mx, o));
        float e = (lane < kK) ? expf(a - mx) : 0.f;
        float s = e;
#pragma unroll
        for (int o = 16; o; o >>= 1) s += __shfl_xor_sync(0xffffffffu, s, o);
        if (lane < kK)
            reinterpret_cast<float2*>(&sp[wid][0])[lane] =
                make_float2(e / s, __int_as_float(id));
        __syncwarp();
        float acc = 0.f;
#pragma unroll
        for (int k2 = 0; k2 < kK / 2; k2++) {
            float4 p = sp[wid][k2];            // LDS.128 broadcast: (a0,id0,a1,id1)
            acc = fmaf(p.x, hb[(size_t)__float_as_int(p.y) * kD + lane], acc);
            acc = fmaf(p.z, hb[(size_t)__float_as_int(p.w) * kD + lane], acc);
        }
        float o = acc + bias;
        g_out1[((size_t)(b * kN + n)) * kD + half * 32 + lane] = o;
        ts += o; tq += o * o;
        __syncwarp();                          // WAR on sp[wid]
    }
    rs[wid][lane] = ts; rq[wid][lane] = tq;
    __syncthreads();
    if (t < 32) {
        float s = 0.f, q = 0.f;
#pragma unroll 8
        for (int w = 0; w < 32; w++) { s += rs[w][t]; q += rq[w][t]; }
        atomicAdd(&g_sum1[half * 32 + t], (double)s);
        atomicAdd(&g_ssq1[half * 32 + t], (double)q);
    }
}

// ---------------- BN affine finalize (inlined by consumers) -----------------
__device__ __forceinline__ void bn_ab(int d, const float* gm, const float* bt,
                                      const double* S, const double* Q,
                                      float& a, float& b) {
    double m = S[d] / (double)kM;
    double var = Q[d] / (double)kM - m * m;
    float inv = (float)(1.0 / sqrt(var + (double)kEps));
    a = gm[d] * inv;
    b = bt[d] - (float)m * a;
}

// ---------------- kernel 5: BN2 statistics ----------------------------------
__global__ void k_stats2(const float* __restrict__ emb,
                         const float* __restrict__ g1, const float* __restrict__ b1v) {
    int t = threadIdx.x;
    int c = t & 63, rg = t >> 6;
    float a1, b1; bn_ab(c, g1, b1v, g_sum1, g_ssq1, a1, b1);
    float ts = 0.f, tq = 0.f;
    int r0 = blockIdx.x * 64;
    for (int i = 0; i < 16; i++) {
        int r = r0 + rg * 16 + i;
        float x = g_out1[(size_t)r * kD + c];
        float y = fmaxf(fmaf(a1, x, b1), 0.f);
        float rep = y * emb[(size_t)(r & (kN - 1)) * kD + c];
        ts += rep; tq += rep * rep;
    }
    __shared__ float rs[4][kD], rq[4][kD];
    rs[rg][c] = ts; rq[rg][c] = tq;
    __syncthreads();
    if (t < kD) {
        float s = 0.f, q = 0.f;
        for (int g = 0; g < 4; g++) { s += rs[g][t]; q += rq[g][t]; }
        atomicAdd(&g_sum2[t], (double)s);
        atomicAdd(&g_ssq2[t], (double)q);
    }
}

// ---------------- kernel 6: final projection --------------------------------
__global__ void k_final(const float* __restrict__ emb, const float* __restrict__ out_w,
                        const float* __restrict__ out_b,
                        const float* __restrict__ g1, const float* __restrict__ b1v,
                        const float* __restrict__ g2, const float* __restrict__ b2v,
                        float* __restrict__ out) {
    int lane = threadIdx.x & 31;
    int gw = (blockIdx.x * blockDim.x + threadIdx.x) >> 5;
    int nw = (gridDim.x * blockDim.x) >> 5;
    float a10, b10, a11, b11, a20, b20, a21, b21;
    bn_ab(lane,      g1, b1v, g_sum1, g_ssq1, a10, b10);
    bn_ab(lane + 32, g1, b1v, g_sum1, g_ssq1, a11, b11);
    bn_ab(lane,      g2, b2v, g_sum2, g_ssq2, a20, b20);
    bn_ab(lane + 32, g2, b2v, g_sum2, g_ssq2, a21, b21);
    float w0 = out_w[lane], w1 = out_w[lane + 32];
    float ob = out_b[0];
    for (int r = gw; r < kM; r += nw) {
        int n = r & (kN - 1);
        float x0 = g_out1[(size_t)r * kD + lane];
        float x1 = g_out1[(size_t)r * kD + lane + 32];
        float y0 = fmaxf(fmaf(a10, x0, b10), 0.f) * emb[(size_t)n * kD + lane];
        float y1 = fmaxf(fmaf(a11, x1, b11), 0.f) * emb[(size_t)n * kD + lane + 32];
        float z0 = fmaxf(fmaf(a20, y0, b20), 0.f);
        float z1 = fmaxf(fmaf(a21, y1, b21), 0.f);
        float sred = z0 * w0 + z1 * w1;
#pragma unroll
        for (int o = 16; o; o >>= 1) sred += __shfl_xor_sync(0xffffffffu, sred, o);
        if (lane == 0) out[r] = sred + ob;
    }
}

// ---------------- launch ----------------------------------------------------
extern "C" void kernel_launch(void* const* d_in, const int* in_sizes, int n_in,
                              void* d_out, int out_size) {
    const float* data     = (const float*)d_in[0];
    // d_in[1] = org_edge_index (int64) — unused by the reference
    const float* emb      = (const float*)d_in[2];
    const float* lin_w    = (const float*)d_in[3];
    const float* att_i    = (const float*)d_in[4];
    const float* att_j    = (const float*)d_in[5];
    const float* aei      = (const float*)d_in[6];
    const float* aej      = (const float*)d_in[7];
    const float* gnn_bias = (const float*)d_in[8];
    const float* g1       = (const float*)d_in[9];
    const float* b1       = (const float*)d_in[10];
    const float* g2       = (const float*)d_in[11];
    const float* b2       = (const float*)d_in[12];
    const float* out_w    = (const float*)d_in[13];
    const float* out_b    = (const float*)d_in[14];
    float* out = (float*)d_out;

    k_cos<<<dim3(16, 16), 256>>>(emb, aei, aej);
    k_h<<<2048, 256>>>(data, lin_w, att_i, att_j);
    k_topk<<<1024, 256>>>();
    k_main<<<128, 1024>>>(gnn_bias);
    k_stats2<<<1024, 256>>>(emb, g1, b1);
    k_final<<<512, 256>>>(emb, out_w, out_b, g1, b1, g2, b2, out);
}

// round 10
// speedup vs baseline: 1.5399x; 1.0120x over previous
#include <cuda_runtime.h>
#include <math.h>

// Problem constants
constexpr int kB = 64, kN = 1024, kF = 16, kD = 64, kK = 20;
constexpr int kM = kB * kN;              // 65536 rows
constexpr float kEps = 1e-5f, kSlope = 0.2f;

// ---------------- scratch (device globals: allocation-free) ----------------
__device__ float  g_h[(size_t)kM * kD];      // 16 MB
__device__ float  g_out1[(size_t)kM * kD];   // 16 MB
__device__ float  g_si[kM];
__device__ float  g_sj[kM];
__device__ float  g_emi[kN];
__device__ float  g_emj[kN];
__device__ float  g_cos[(size_t)kN * kN];    // 4 MB
__device__ int    g_idx[kN * kK];
__device__ float2 g_alpha[(size_t)kM * kK];  // 10.5 MB packed (alpha, id)
__device__ double g_sum1[kD], g_ssq1[kD], g_sum2[kD], g_ssq2[kD];

// ---------------- kernel 1: cosine Gram + norms + emb-att dots + zeroing ----
__global__ void k_cos(const float* __restrict__ emb,
                      const float* __restrict__ aei,
                      const float* __restrict__ aej) {
    __shared__ float As[kD][65];
    __shared__ float Bs[kD][65];
    __shared__ float rnA[64], rnB[64];
    int t = threadIdx.x;
    int bn = blockIdx.y * 64, bm = blockIdx.x * 64;
    if (blockIdx.x == 0 && blockIdx.y == 0 && t < kD) {
        g_sum1[t] = 0.0; g_ssq1[t] = 0.0; g_sum2[t] = 0.0; g_ssq2[t] = 0.0;
    }
    for (int idx = t; idx < 64 * 64; idx += 256) {
        int r = idx >> 6, k = idx & 63;
        As[k][r] = emb[(size_t)(bn + r) * kD + k];
        Bs[k][r] = emb[(size_t)(bm + r) * kD + k];
    }
    __syncthreads();
    if (t < 64) {
        float s = 0.f;
        for (int k = 0; k < 64; k++) { float v = As[k][t]; s += v * v; }
        rnA[t] = 1.0f / sqrtf(s);
    } else if (t < 128) {
        int r = t - 64;
        float s = 0.f;
        for (int k = 0; k < 64; k++) { float v = Bs[k][r]; s += v * v; }
        rnB[r] = 1.0f / sqrtf(s);
    } else if (blockIdx.x == 0) {
        int r = (t - 128) & 63;
        const float* av = (t < 192) ? aei : aej;
        float s = 0.f;
        for (int k = 0; k < 64; k++) s += As[k][r] * av[k];
        if (t < 192) g_emi[bn + r] = s; else g_emj[bn + r] = s;
    }
    int tx = t & 15, ty = t >> 4;
    float acc[4][4] = {};
#pragma unroll 4
    for (int k = 0; k < 64; k++) {
        float a[4], b[4];
#pragma unroll
        for (int i = 0; i < 4; i++) { a[i] = As[k][ty * 4 + i]; b[i] = Bs[k][tx * 4 + i]; }
#pragma unroll
        for (int i = 0; i < 4; i++)
#pragma unroll
            for (int j = 0; j < 4; j++) acc[i][j] += a[i] * b[j];
    }
    __syncthreads();
#pragma unroll
    for (int i = 0; i < 4; i++) {
        int r = bn + ty * 4 + i;
        float rn = rnA[ty * 4 + i];
#pragma unroll
        for (int j = 0; j < 4; j++) {
            int c = bm + tx * 4 + j;
            g_cos[(size_t)r * kN + c] = acc[i][j] * rn * rnB[tx * 4 + j];
        }
    }
}

// ---------------- kernel 2: h = data @ lin_w^T, plus s_i / s_j --------------
__global__ void k_h(const float* __restrict__ data, const float* __restrict__ lin_w,
                    const float* __restrict__ att_i, const float* __restrict__ att_j) {
    __shared__ float lw[kF][kD];
    for (int idx = threadIdx.x; idx < kF * kD; idx += blockDim.x) {
        int f = idx >> 6, d = idx & 63;
        lw[f][d] = lin_w[d * kF + f];
    }
    __syncthreads();
    int lane = threadIdx.x & 31;
    int gw = (blockIdx.x * blockDim.x + threadIdx.x) >> 5;
    int nw = (gridDim.x * blockDim.x) >> 5;
    float ai0 = att_i[lane], ai1 = att_i[lane + 32];
    float aj0 = att_j[lane], aj1 = att_j[lane + 32];
    for (int r = gw; r < kM; r += nw) {
        const float4* dp = reinterpret_cast<const float4*>(data + (size_t)r * kF);
        float4 q0 = dp[0], q1 = dp[1], q2 = dp[2], q3 = dp[3];
        float df[16] = {q0.x, q0.y, q0.z, q0.w, q1.x, q1.y, q1.z, q1.w,
                        q2.x, q2.y, q2.z, q2.w, q3.x, q3.y, q3.z, q3.w};
        float h0 = 0.f, h1 = 0.f;
#pragma unroll
        for (int f = 0; f < 16; f++) {
            h0 += df[f] * lw[f][lane];
            h1 += df[f] * lw[f][lane + 32];
        }
        g_h[(size_t)r * kD + lane] = h0;
        g_h[(size_t)r * kD + lane + 32] = h1;
        float si = h0 * ai0 + h1 * ai1;
        float sj = h0 * aj0 + h1 * aj1;
#pragma unroll
        for (int o = 16; o; o >>= 1) {
            si += __shfl_xor_sync(0xffffffffu, si, o);
            sj += __shfl_xor_sync(0xffffffffu, sj, o);
        }
        if (lane == 0) {
            int n = r & (kN - 1);
            g_si[r] = si + g_emi[n];
            g_sj[r] = sj + g_emj[n];
        }
    }
}

// ---------------- kernel 3: exact top-20 via 4-pass 8-bit radix select ------
// Warp-aggregated histogram atomics (__match_any_sync) — cos values cluster
// into few buckets, so raw smem atomics serialize badly.
__global__ void k_topk() {
    __shared__ unsigned sv[kN];
    __shared__ int hist[256];
    __shared__ int suf[256];
    __shared__ int tie[kN];
    __shared__ int s_digit, s_above, s_need, s_cntA, s_cntT, s_sel;
    __shared__ int wmin[8];
    int n = blockIdx.x, t = threadIdx.x;
    int lane = t & 31, wid = t >> 5;
    const unsigned* row = reinterpret_cast<const unsigned*>(g_cos + (size_t)n * kN);
#pragma unroll
    for (int i = 0; i < 4; i++) {
        unsigned x = row[t + 256 * i];
        x ^= (x & 0x80000000u) ? 0xFFFFFFFFu : 0x80000000u;  // order-preserving
        sv[t + 256 * i] = x;
    }
    if (t == 0) { s_need = kK; s_cntA = 0; s_cntT = 0; }
    unsigned prefix = 0;
    for (int shift = 24; shift >= 0; shift -= 8) {
        hist[t] = 0;
        __syncthreads();
        unsigned mask = (shift == 24) ? 0u : (0xFFFFFFFFu << (shift + 8));
#pragma unroll
        for (int i = 0; i < 4; i++) {
            unsigned x = sv[t + 256 * i];
            bool pred = (x & mask) == prefix;
            int d = (x >> shift) & 0xFF;
            int key = pred ? d : (0x100 + lane);   // inactive lanes: unique keys
            unsigned peers = __match_any_sync(0xffffffffu, key);
            if (pred && ((peers & (peers - 1u) & ((1u << lane) - 1u)) == 0u)
                     && (peers & ((1u << lane) - 1u)) == 0u)
                atomicAdd(&hist[d], __popc(peers));
        }
        __syncthreads();
        if (wid == 0) {  // suffix sums: suf[e] = count of digit >= e
            int base = 255 - 8 * lane;
            int loc[8], s = 0;
#pragma unroll
            for (int j = 0; j < 8; j++) { loc[j] = hist[base - j]; s += loc[j]; }
            int run = s;
#pragma unroll
            for (int off = 1; off < 32; off <<= 1) {
                int v = __shfl_up_sync(0xffffffffu, run, off);
                if (lane >= off) run += v;
            }
            int acc = run - s;
#pragma unroll
            for (int j = 0; j < 8; j++) { acc += loc[j]; suf[base - j] = acc; }
        }
        __syncthreads();
        int need = s_need;
        int above = (t == 255) ? 0 : suf[t + 1];
        if (suf[t] >= need && above < need) { s_digit = t; s_above = above; }
        __syncthreads();
        prefix |= ((unsigned)s_digit) << shift;
        if (t == 0) s_need -= s_above;
        __syncthreads();
    }
    unsigned T = prefix;  // exact K-th largest (transformed)
#pragma unroll
    for (int i = 0; i < 4; i++) {
        int m = t + 256 * i;
        unsigned x = sv[m];
        if (x > T)      { int p = atomicAdd(&s_cntA, 1); g_idx[n * kK + p] = m; }
        else if (x == T){ int p = atomicAdd(&s_cntT, 1); tie[p] = m; }
    }
    __syncthreads();
    int needT = kK - s_cntA;
    if (s_cntT == needT) {
        if (t < needT) g_idx[n * kK + s_cntA + t] = tie[t];
    } else {
        for (int r = 0; r < needT; r++) {
            int best = 0x7fffffff;
            for (int i = t; i < s_cntT; i += 256) best = min(best, tie[i]);
#pragma unroll
            for (int o = 16; o; o >>= 1) best = min(best, __shfl_xor_sync(0xffffffffu, best, o));
            if (lane == 0) wmin[wid] = best;
            __syncthreads();
            if (t == 0) {
                int m = 0x7fffffff;
                for (int w = 0; w < 8; w++) m = min(m, wmin[w]);
                g_idx[n * kK + s_cntA + r] = m;
                s_sel = m;
            }
            __syncthreads();
            for (int i = t; i < s_cntT; i += 256) if (tie[i] == s_sel) tie[i] = 0x7fffffff;
            __syncthreads();
        }
    }
}

// ---------------- kernel 3b: softmax -> packed (alpha, id) per row ----------
__global__ void k_alpha() {
    int lane = threadIdx.x & 31;
    int gw = (blockIdx.x * blockDim.x + threadIdx.x) >> 5;
    int nw = (gridDim.x * blockDim.x) >> 5;
    for (int r = gw; r < kM; r += nw) {
        int b = r >> 10, n = r & (kN - 1);
        float a = -INFINITY; int id = 0;
        if (lane < kK) {
            id = g_idx[n * kK + lane];
            a = g_si[r] + g_sj[b * kN + id];
            a = a > 0.f ? a : kSlope * a;      // leaky_relu(0.2)
        }
        float mx = a;
#pragma unroll
        for (int o = 16; o; o >>= 1) mx = fmaxf(mx, __shfl_xor_sync(0xffffffffu, mx, o));
        float e = (lane < kK) ? expf(a - mx) : 0.f;
        float s = e;
#pragma unroll
        for (int o = 16; o; o >>= 1) s += __shfl_xor_sync(0xffffffffu, s, o);
        if (lane < kK)
            g_alpha[(size_t)r * kK + lane] = make_float2(e / s, __int_as_float(id));
    }
}

// ---------------- kernel 4: vectorized L1-resident gather + BN1 stats -------
// Block of 1024 threads per (b, d-half). Each warp handles 4 rows at once:
// lanes split into 4 sub-groups of 8; each sub-group covers its row-half with
// float4 (LDG.128). Alpha pairs preloaded to smem; no softmax in the loop.
__global__ void __launch_bounds__(1024, 1) k_main(const float* __restrict__ gnn_bias) {
    __shared__ float4 sp4[32][40];             // 20 KB: per-warp 4 rows x 20 pairs
    __shared__ float  rs[32][32], rq[32][32];  // 8 KB
    int t = threadIdx.x, lane = t & 31, wid = t >> 5;
    int sub = lane >> 3, li = lane & 7;
    int b = blockIdx.x >> 1, half = blockIdx.x & 1;
    const float4* hb4 = reinterpret_cast<const float4*>(
        g_h + (size_t)b * kN * kD + half * 32);
    const float4* ga4 = reinterpret_cast<const float4*>(g_alpha);  // 10 f4/row
    float4 bias4 = reinterpret_cast<const float4*>(gnn_bias)[half * 8 + li];
    float4 ts4 = make_float4(0.f, 0.f, 0.f, 0.f);
    float4 tq4 = make_float4(0.f, 0.f, 0.f, 0.f);
#pragma unroll 1
    for (int g = 0; g < 8; g++) {
        int n0 = (g * 32 + wid) * 4;
        size_t rowbase = (size_t)b * kN + n0;
        size_t gbase = rowbase * 10;           // float4 units (40 per 4 rows)
        sp4[wid][lane] = ga4[gbase + lane];
        if (lane < 8) sp4[wid][32 + lane] = ga4[gbase + 32 + lane];
        __syncwarp();
        float4 acc = make_float4(0.f, 0.f, 0.f, 0.f);
#pragma unroll
        for (int k2 = 0; k2 < kK / 2; k2++) {
            float4 p = sp4[wid][sub * 10 + k2];   // (a0,id0,a1,id1) broadcast x4
            float4 v0 = hb4[(size_t)__float_as_int(p.y) * 16 + li];
            float4 v1 = hb4[(size_t)__float_as_int(p.w) * 16 + li];
            acc.x = fmaf(p.x, v0.x, fmaf(p.z, v1.x, acc.x));
            acc.y = fmaf(p.x, v0.y, fmaf(p.z, v1.y, acc.y));
            acc.z = fmaf(p.x, v0.z, fmaf(p.z, v1.z, acc.z));
            acc.w = fmaf(p.x, v0.w, fmaf(p.z, v1.w, acc.w));
        }
        float4 o4;
        o4.x = acc.x + bias4.x; o4.y = acc.y + bias4.y;
        o4.z = acc.z + bias4.z; o4.w = acc.w + bias4.w;
        reinterpret_cast<float4*>(
            g_out1 + (rowbase + sub) * kD + half * 32)[li] = o4;
        ts4.x += o4.x; ts4.y += o4.y; ts4.z += o4.z; ts4.w += o4.w;
        tq4.x = fmaf(o4.x, o4.x, tq4.x); tq4.y = fmaf(o4.y, o4.y, tq4.y);
        tq4.z = fmaf(o4.z, o4.z, tq4.z); tq4.w = fmaf(o4.w, o4.w, tq4.w);
        __syncwarp();                          // WAR on sp4[wid]
    }
    // reduce the 4 sub-groups (lanes li, li+8, li+16, li+24)
#pragma unroll
    for (int off = 8; off <= 16; off <<= 1) {
        ts4.x += __shfl_xor_sync(0xffffffffu, ts4.x, off);
        ts4.y += __shfl_xor_sync(0xffffffffu, ts4.y, off);
        ts4.z += __shfl_xor_sync(0xffffffffu, ts4.z, off);
        ts4.w += __shfl_xor_sync(0xffffffffu, ts4.w, off);
        tq4.x += __shfl_xor_sync(0xffffffffu, tq4.x, off);
        tq4.y += __shfl_xor_sync(0xffffffffu, tq4.y, off);
        tq4.z += __shfl_xor_sync(0xffffffffu, tq4.z, off);
        tq4.w += __shfl_xor_sync(0xffffffffu, tq4.w, off);
    }
    if (sub == 0) {
        reinterpret_cast<float4*>(&rs[wid][0])[li] = ts4;
        reinterpret_cast<float4*>(&rq[wid][0])[li] = tq4;
    }
    __syncthreads();
    if (t < 32) {
        float s = 0.f, q = 0.f;
#pragma unroll 8
        for (int w = 0; w < 32; w++) { s += rs[w][t]; q += rq[w][t]; }
        atomicAdd(&g_sum1[half * 32 + t], (double)s);
        atomicAdd(&g_ssq1[half * 32 + t], (double)q);
    }
}

// ---------------- BN affine finalize (inlined by consumers) -----------------
__device__ __forceinline__ void bn_ab(int d, const float* gm, const float* bt,
                                      const double* S, const double* Q,
                                      float& a, float& b) {
    double m = S[d] / (double)kM;
    double var = Q[d] / (double)kM - m * m;
    float inv = (float)(1.0 / sqrt(var + (double)kEps));
    a = gm[d] * inv;
    b = bt[d] - (float)m * a;
}

// ---------------- kernel 5: BN2 statistics ----------------------------------
__global__ void k_stats2(const float* __restrict__ emb,
                         const float* __restrict__ g1, const float* __restrict__ b1v) {
    int t = threadIdx.x;
    int c = t & 63, rg = t >> 6;
    float a1, b1; bn_ab(c, g1, b1v, g_sum1, g_ssq1, a1, b1);
    float ts = 0.f, tq = 0.f;
    int r0 = blockIdx.x * 64;
    for (int i = 0; i < 16; i++) {
        int r = r0 + rg * 16 + i;
        float x = g_out1[(size_t)r * kD + c];
        float y = fmaxf(fmaf(a1, x, b1), 0.f);
        float rep = y * emb[(size_t)(r & (kN - 1)) * kD + c];
        ts += rep; tq += rep * rep;
    }
    __shared__ float rs[4][kD], rq[4][kD];
    rs[rg][c] = ts; rq[rg][c] = tq;
    __syncthreads();
    if (t < kD) {
        float s = 0.f, q = 0.f;
        for (int g = 0; g < 4; g++) { s += rs[g][t]; q += rq[g][t]; }
        atomicAdd(&g_sum2[t], (double)s);
        atomicAdd(&g_ssq2[t], (double)q);
    }
}

// ---------------- kernel 6: final projection --------------------------------
__global__ void k_final(const float* __restrict__ emb, const float* __restrict__ out_w,
                        const float* __restrict__ out_b,
                        const float* __restrict__ g1, const float* __restrict__ b1v,
                        const float* __restrict__ g2, const float* __restrict__ b2v,
                        float* __restrict__ out) {
    int lane = threadIdx.x & 31;
    int gw = (blockIdx.x * blockDim.x + threadIdx.x) >> 5;
    int nw = (gridDim.x * blockDim.x) >> 5;
    float a10, b10, a11, b11, a20, b20, a21, b21;
    bn_ab(lane,      g1, b1v, g_sum1, g_ssq1, a10, b10);
    bn_ab(lane + 32, g1, b1v, g_sum1, g_ssq1, a11, b11);
    bn_ab(lane,      g2, b2v, g_sum2, g_ssq2, a20, b20);
    bn_ab(lane + 32, g2, b2v, g_sum2, g_ssq2, a21, b21);
    float w0 = out_w[lane], w1 = out_w[lane + 32];
    float ob = out_b[0];
    for (int r = gw; r < kM; r += nw) {
        int n = r & (kN - 1);
        float x0 = g_out1[(size_t)r * kD + lane];
        float x1 = g_out1[(size_t)r * kD + lane + 32];
        float y0 = fmaxf(fmaf(a10, x0, b10), 0.f) * emb[(size_t)n * kD + lane];
        float y1 = fmaxf(fmaf(a11, x1, b11), 0.f) * emb[(size_t)n * kD + lane + 32];
        float z0 = fmaxf(fmaf(a20, y0, b20), 0.f);
        float z1 = fmaxf(fmaf(a21, y1, b21), 0.f);
        float sred = z0 * w0 + z1 * w1;
#pragma unroll
        for (int o = 16; o; o >>= 1) sred += __shfl_xor_sync(0xffffffffu, sred, o);
        if (lane == 0) out[r] = sred + ob;
    }
}

// ---------------- launch ----------------------------------------------------
extern "C" void kernel_launch(void* const* d_in, const int* in_sizes, int n_in,
                              void* d_out, int out_size) {
    const float* data     = (const float*)d_in[0];
    // d_in[1] = org_edge_index (int64) — unused by the reference
    const float* emb      = (const float*)d_in[2];
    const float* lin_w    = (const float*)d_in[3];
    const float* att_i    = (const float*)d_in[4];
    const float* att_j    = (const float*)d_in[5];
    const float* aei      = (const float*)d_in[6];
    const float* aej      = (const float*)d_in[7];
    const float* gnn_bias = (const float*)d_in[8];
    const float* g1       = (const float*)d_in[9];
    const float* b1       = (const float*)d_in[10];
    const float* g2       = (const float*)d_in[11];
    const float* b2       = (const float*)d_in[12];
    const float* out_w    = (const float*)d_in[13];
    const float* out_b    = (const float*)d_in[14];
    float* out = (float*)d_out;

    k_cos<<<dim3(16, 16), 256>>>(emb, aei, aej);
    k_h<<<2048, 256>>>(data, lin_w, att_i, att_j);
    k_topk<<<1024, 256>>>();
    k_alpha<<<1024, 256>>>();
    k_main<<<128, 1024>>>(gnn_bias);
    k_stats2<<<1024, 256>>>(emb, g1, b1);
    k_final<<<512, 256>>>(emb, out_w, out_b, g1, b1, g2, b2, out);
}